// round 8
// baseline (speedup 1.0000x reference)
#include <cuda_runtime.h>
#include <cuda_bf16.h>
#include <math.h>

#define NB 256
#define BATCHN 128
#define NSTEPS 100
#define MAXEV 5
#define HID 64
#define NTH 256
#define NWARP (NTH/32)
#define SEGCAP 770
#define MARGIN 1.0f

#define BAR_SYNC(id,cnt)   asm volatile("bar.sync %0, %1;"   :: "r"(id), "r"(cnt) : "memory")
#define BAR_ARRIVE(id,cnt) asm volatile("bar.arrive %0, %1;" :: "r"(id), "r"(cnt) : "memory")

__device__ __forceinline__ float silu_f(float x) {
    return x / (1.0f + expf(-x));
}

__global__ __launch_bounds__(NTH, 1)
void hybrid_rollout(const float* __restrict__ g_state,
                    const float* __restrict__ g_radii,
                    const float* __restrict__ g_W1,
                    const float* __restrict__ g_b1,
                    const float* __restrict__ g_W2,
                    const float* __restrict__ g_b2,
                    const float* __restrict__ g_W3,
                    const float* __restrict__ g_b3,
                    float* __restrict__ g_out)
{
    __shared__ float4 own[NB];                 // this block's batch element
    __shared__ float4 bb0[NB];                 // private copy of batch element 0
    __shared__ float2 posA[NB];                // position mirror of bb0 (broad phase)
    __shared__ float4 w2q[16*HID];             // w2q[k4*HID+o] = W2[o][4k4..4k4+3]
    __shared__ float w1s[2*HID];
    __shared__ float b1s[HID], b2s[HID], w3s[HID];
    __shared__ float4 h1q[2*16];               // h1 as float4 (layer-1 activations)
    __shared__ float h2buf[2*HID];
    __shared__ unsigned long long redB[NWARP], redW[NWARP];
    __shared__ float vmaxW[NWARP];
    __shared__ int nCandW[NWARP];
    __shared__ int candList[NWARP*SEGCAP];     // per-warp segments, packed (lo<<8)|hi
    __shared__ int sVmax2i;                    // float bits of max speed^2 over bb0
    __shared__ float sMotion;
    __shared__ int sOverflow;
    __shared__ float sb3, srr;

    const int tid  = threadIdx.x;
    const int bidx = blockIdx.x;
    const int i0   = tid;                      // one ball per thread
    const int lane = tid & 31;
    const int warp = tid >> 5;

    // ---- setup ----
    {
        float4 v = reinterpret_cast<const float4*>(g_state)[bidx*NB + tid];
        own[tid] = v;
        float4 c = reinterpret_cast<const float4*>(g_state)[tid];
        bb0[tid] = c;
        posA[tid] = make_float2(c.x, c.y);
        reinterpret_cast<float4*>(g_out)[bidx*NB + tid] = v;
    }
    for (int q = tid; q < 16*HID; q += NTH) {
        int o = q & 63, k4 = q >> 6;
        const float* src = g_W2 + o*HID + k4*4;
        w2q[q] = make_float4(src[0], src[1], src[2], src[3]);
    }
    if (tid < 2*HID) w1s[tid] = g_W1[tid];
    if (tid < HID) { b1s[tid] = g_b1[tid]; b2s[tid] = g_b2[tid]; w3s[tid] = g_W3[tid]; }
    if (tid == 0) {
        sb3 = g_b3[0]; srr = g_radii[0];
        sMotion = 1e30f; sVmax2i = 0; sOverflow = 0;
    }
    __syncthreads();

    const float rr    = srr;
    const float two_r = rr + rr;
    const float cut   = two_r + 0.051f;        // exact narrow cutoff (gap>0.05 -> done)
    const float c2    = cut * cut;
    const float cute  = cut + MARGIN;          // broad-phase cutoff
    const float c2e   = cute * cute;
    const float b3v   = sb3;

    for (int s = 0; s < NSTEPS; ++s) {
        const float t_s = (float)s * 0.05f;
        const float t_e = t_s + 0.05f;
        float t_c = t_s;

        for (int ev = 0; ev < MAXEV; ++ev) {
            // ================= P0: detection =================
            const bool rebuild = (sOverflow != 0) || (sMotion >= MARGIN);
            const float4 me = bb0[i0];
            unsigned long long bk = ~0ull, wk = ~0ull;

            if (rebuild) {
                // warp-max of speed^2 (no atomics)
                float m = me.z*me.z + me.w*me.w;
                #pragma unroll
                for (int off = 16; off > 0; off >>= 1)
                    m = fmaxf(m, __shfl_down_sync(0xFFFFFFFFu, m, off));
                if (lane == 0) vmaxW[warp] = m;

                int cnt = 0;
                const int segBase = warp * SEGCAP;
                for (int d = 1; d <= 128; ++d) {
                    if (d == 128 && i0 >= 128) break;      // warp-uniform
                    int j = (i0 + d) & (NB-1);
                    float2 pj = posA[j];
                    float dx = pj.x - me.x, dy = pj.y - me.y;
                    float d2 = dx*dx + dy*dy;
                    bool push = (d2 <= c2e);
                    unsigned msk = __ballot_sync(0xFFFFFFFFu, push);
                    if (push) {
                        int lo = (i0 < j) ? i0 : j;
                        int hi = (i0 < j) ? j : i0;
                        int slot = cnt + __popc(msk & ((1u << lane) - 1u));
                        if (slot < SEGCAP) candList[segBase + slot] = (lo << 8) | hi;
                        float4 oj = bb0[j];
                        float dvx = oj.z - me.z, dvy = oj.w - me.w;
                        if (dvx*dx + dvy*dy < 0.0f && d2 <= c2) {
                            unsigned long long key =
                                ((unsigned long long)__float_as_uint(d2) << 32) |
                                (unsigned)((lo << 8) | hi);
                            if (key < bk) bk = key;
                        }
                    }
                    cnt += __popc(msk);
                }
                if (lane == 0) nCandW[warp] = cnt;
            } else {
                const int seg  = tid & (NWARP-1);
                const int e0   = tid >> 3;                 // 0..31
                int n = nCandW[seg]; if (n > SEGCAP) n = SEGCAP;
                const int base = seg * SEGCAP;
                for (int e = e0; e < n; e += 32) {
                    int p = candList[base + e];
                    int lo = p >> 8, hi = p & 255;
                    float4 si = bb0[lo], sj = bb0[hi];
                    float dx = sj.x - si.x, dy = sj.y - si.y;
                    float d2 = dx*dx + dy*dy;
                    float dvx = sj.z - si.z, dvy = sj.w - si.w;
                    if (dvx*dx + dvy*dy < 0.0f && d2 <= c2) {
                        unsigned long long key =
                            ((unsigned long long)__float_as_uint(d2) << 32) | (unsigned)p;
                        if (key < bk) bk = key;
                    }
                }
            }

            // wall candidates (every thread owns one ball)
            {
                float gs[4]; bool vs[4];
                gs[0] = me.x - rr;          vs[0] = me.z < 0.0f;
                gs[1] = 10.0f - me.x - rr;  vs[1] = me.z > 0.0f;
                gs[2] = me.y - rr;          vs[2] = me.w < 0.0f;
                gs[3] = 10.0f - me.y - rr;  vs[3] = me.w > 0.0f;
                #pragma unroll
                for (int w = 0; w < 4; ++w) {
                    if (vs[w]) {
                        unsigned u = __float_as_uint(gs[w]);
                        u = (u & 0x80000000u) ? ~u : (u | 0x80000000u);
                        unsigned long long key = ((unsigned long long)u << 32) | (unsigned)(i0*4 + w);
                        if (key < wk) wk = key;
                    }
                }
            }

            // warp tree -> lane0 STS -> BAR -> redundant 8-way butterfly fold
            #pragma unroll
            for (int off = 16; off > 0; off >>= 1) {
                unsigned long long ob = __shfl_down_sync(0xFFFFFFFFu, bk, off);
                unsigned long long ow = __shfl_down_sync(0xFFFFFFFFu, wk, off);
                if (ob < bk) bk = ob;
                if (ow < wk) wk = ow;
            }
            if (lane == 0) { redB[warp] = bk; redW[warp] = wk; }
            __syncthreads();                              // ---- BAR A ----

            if (rebuild && tid == NTH-1) {
                float vm = vmaxW[0];
                #pragma unroll
                for (int w = 1; w < NWARP; ++w) vm = fmaxf(vm, vmaxW[w]);
                sVmax2i = __float_as_int(vm);
                int ov = 0;
                #pragma unroll
                for (int w = 0; w < NWARP; ++w) ov |= (nCandW[w] > SEGCAP);
                if (ov) sOverflow = 1;
                sMotion = 0.0f;
            }

            bk = redB[lane & (NWARP-1)];
            wk = redW[lane & (NWARP-1)];
            #pragma unroll
            for (int off = 4; off > 0; off >>= 1) {
                unsigned long long ob = __shfl_xor_sync(0xFFFFFFFFu, bk, off);
                unsigned long long ow = __shfl_xor_sync(0xFFFFFFFFu, wk, off);
                if (ob < bk) bk = ob;
                if (ow < wk) wk = ow;
            }

            float gapB = 1e30f, gapW = 1e30f;
            if (bk != ~0ull) gapB = sqrtf(__uint_as_float((unsigned)(bk >> 32))) - two_r;
            if (wk != ~0ull) {
                unsigned u = (unsigned)(wk >> 32);
                u = (u & 0x80000000u) ? (u ^ 0x80000000u) : ~u;
                gapW = __uint_as_float(u);
            }
            const bool  is_ball = (gapB <= gapW);
            const float gap     = is_ball ? gapB : gapW;
            if (gap > 0.05f) break;                        // no_event -> done

            // redundant decode + flags on ALL threads
            int iA, iB = 0, wsel = 0;
            float app;
            if (is_ball) {
                iA = (int)(((unsigned)bk >> 8) & 255u);
                iB = (int)((unsigned)bk & 255u);
                float4 pi = bb0[iA], pj = bb0[iB];
                float nx = pj.x - pi.x, ny = pj.y - pi.y;
                float L = sqrtf(nx*nx + ny*ny);
                app = -(((pj.z - pi.z)*nx)/L + ((pj.w - pi.w)*ny)/L);
            } else {
                iA = (int)((unsigned)wk >> 2);
                wsel = (int)((unsigned)wk & 3u);
                float4 pi = bb0[iA];
                app = fabsf(fmaxf(pi.z, pi.w));
            }
            const float t_ev  = t_c + gap / fmaxf(app, 1e-6f);
            const bool case_a = (gap <= 0.0f);
            const bool case_b = (!case_a) && (app > 1e-6f) && (t_ev < t_e);
            if (!case_a && !case_b) break;                 // done
            const float dte = case_b ? ((t_ev > t_c + 1e-10f) ? (t_ev - t_c) : 0.0f) : 0.0f;
            if (case_b) t_c = t_ev;

            if (is_ball) {
                if (tid < 2*HID) {
                    // integrate own ball (iA/iB excluded -> MLP can read them pre-event)
                    if (tid != iA && tid != iB) {
                        float4 v = own[tid];
                        v.x = fmaf(v.z, dte, v.x); v.y = fmaf(v.w, dte, v.y);
                        own[tid] = v;
                        float4 c = bb0[tid];
                        c.x = fmaf(c.z, dte, c.x); c.y = fmaf(c.w, dte, c.y);
                        bb0[tid] = c;
                        posA[tid] = make_float2(c.x, c.y);
                    }
                    // h1
                    int sel = tid >> 6, o = tid & (HID-1);
                    const float4* S = sel ? bb0 : own;
                    float4 si = S[iA], sj = S[iB];
                    float six = fmaf(si.z, dte, si.x), siy = fmaf(si.w, dte, si.y);
                    float sjx = fmaf(sj.z, dte, sj.x), sjy = fmaf(sj.w, dte, sj.y);
                    float dx = sjx - six, dy = sjy - siy;
                    float dist = fmaxf(sqrtf(dx*dx + dy*dy), 1e-8f);
                    float nx = dx / dist, ny = dy / dist;
                    float ap = (sj.z - si.z)*nx + (sj.w - si.w)*ny;
                    float pre = dist*w1s[2*o] + ap*w1s[2*o+1] + b1s[o];
                    reinterpret_cast<float*>(h1q)[sel*HID + o] = silu_f(pre);
                    BAR_SYNC(3, 128);                     // MLP-internal (h1 ready)
                    // h2: float4 weights, 4 accumulators
                    const float4* H = &h1q[sel*16];
                    float a0 = 0.f, a1 = 0.f, a2 = 0.f, a3 = 0.f;
                    #pragma unroll
                    for (int k4 = 0; k4 < 16; k4 += 4) {
                        float4 w0 = w2q[(k4+0)*HID + o], hh0 = H[k4+0];
                        a0 = fmaf(w0.x,hh0.x,a0); a0 = fmaf(w0.y,hh0.y,a0);
                        a0 = fmaf(w0.z,hh0.z,a0); a0 = fmaf(w0.w,hh0.w,a0);
                        float4 w1v = w2q[(k4+1)*HID + o], hh1 = H[k4+1];
                        a1 = fmaf(w1v.x,hh1.x,a1); a1 = fmaf(w1v.y,hh1.y,a1);
                        a1 = fmaf(w1v.z,hh1.z,a1); a1 = fmaf(w1v.w,hh1.w,a1);
                        float4 w2v = w2q[(k4+2)*HID + o], hh2 = H[k4+2];
                        a2 = fmaf(w2v.x,hh2.x,a2); a2 = fmaf(w2v.y,hh2.y,a2);
                        a2 = fmaf(w2v.z,hh2.z,a2); a2 = fmaf(w2v.w,hh2.w,a2);
                        float4 w3v = w2q[(k4+3)*HID + o], hh3 = H[k4+3];
                        a3 = fmaf(w3v.x,hh3.x,a3); a3 = fmaf(w3v.y,hh3.y,a3);
                        a3 = fmaf(w3v.z,hh3.z,a3); a3 = fmaf(w3v.w,hh3.w,a3);
                    }
                    float acc = ((b2s[o] + a0) + a1) + (a2 + a3);
                    h2buf[sel*HID + o] = w3s[o] * silu_f(acc);
                    BAR_SYNC(1, NTH);                     // waits MLP warps + integrator arrivals
                    // h3 on warps 0 and 2
                    if (warp == 0 || warp == 2) {
                        int sl = warp >> 1;
                        float v = h2buf[sl*HID + lane] + h2buf[sl*HID + 32 + lane];
                        #pragma unroll
                        for (int off = 16; off > 0; off >>= 1)
                            v += __shfl_down_sync(0xFFFFFFFFu, v, off);
                        if (lane == 0) {
                            float impv = v + b3v;
                            float4* S2 = sl ? bb0 : own;
                            float4 ti = S2[iA], tj = S2[iB];   // still pre-event
                            float tix = fmaf(ti.z, dte, ti.x), tiy = fmaf(ti.w, dte, ti.y);
                            float tjx = fmaf(tj.z, dte, tj.x), tjy = fmaf(tj.w, dte, tj.y);
                            float ddx = tjx - tix, ddy = tjy - tiy;
                            float dst = fmaxf(sqrtf(ddx*ddx + ddy*ddy), 1e-8f);
                            float nnx = ddx/dst, nny = ddy/dst;
                            float niz = ti.z + impv*nnx, niw = ti.w + impv*nny;
                            float njz = tj.z - impv*nnx, njw = tj.w - impv*nny;
                            S2[iA] = make_float4(tix, tiy, niz, niw);
                            S2[iB] = make_float4(tjx, tjy, njz, njw);
                            if (sl == 1) {
                                posA[iA] = make_float2(tix, tiy);
                                posA[iB] = make_float2(tjx, tjy);
                                float sp = fmaxf(niz*niz + niw*niw, njz*njz + njw*njw);
                                atomicMax(&sVmax2i, __float_as_int(sp));
                            }
                        }
                    }
                } else {
                    BAR_ARRIVE(1, NTH);                   // decode reads released
                    if (tid != iA && tid != iB) {
                        float4 v = own[tid];
                        v.x = fmaf(v.z, dte, v.x); v.y = fmaf(v.w, dte, v.y);
                        own[tid] = v;
                        float4 c = bb0[tid];
                        c.x = fmaf(c.z, dte, c.x); c.y = fmaf(c.w, dte, c.y);
                        bb0[tid] = c;
                        posA[tid] = make_float2(c.x, c.y);
                    }
                    if (tid == NTH-1)
                        sMotion += 2.0f * sqrtf(__int_as_float(sVmax2i)) * dte;
                }
            } else {
                if (warp == 0) {
                    BAR_SYNC(2, NTH);                     // all decode reads drained
                    if (tid != iA) {
                        float4 v = own[tid];
                        v.x = fmaf(v.z, dte, v.x); v.y = fmaf(v.w, dte, v.y);
                        own[tid] = v;
                        float4 c = bb0[tid];
                        c.x = fmaf(c.z, dte, c.x); c.y = fmaf(c.w, dte, c.y);
                        bb0[tid] = c;
                        posA[tid] = make_float2(c.x, c.y);
                    }
                    if (tid < 2) {
                        const float4 si = tid ? bb0[iA] : own[iA];
                        float six = fmaf(si.z, dte, si.x), siy = fmaf(si.w, dte, si.y);
                        float wnx = 0.0f, wny = 0.0f, wp = 0.0f;
                        if      (wsel == 0) { wnx =  1.0f; }
                        else if (wsel == 1) { wnx = -1.0f; wp = -10.0f; }
                        else if (wsel == 2) { wny =  1.0f; }
                        else                { wny = -1.0f; wp = -10.0f; }
                        float vn  = si.z*wnx + si.w*wny;
                        float nvx = si.z - 2.0f*vn*wnx;
                        float nvy = si.w - 2.0f*vn*wny;
                        float pn  = six*wnx + siy*wny;
                        float pen = fmaxf(wp + rr - pn, 0.0f);
                        float4 res = make_float4(six + pen*wnx, siy + pen*wny, nvx, nvy);
                        float4* S = tid ? bb0 : own;
                        S[iA] = res;
                        if (tid == 1) {
                            posA[iA] = make_float2(res.x, res.y);
                            sMotion += 2.0f * sqrtf(__int_as_float(sVmax2i)) * dte + pen;
                        }
                    }
                } else {
                    BAR_ARRIVE(2, NTH);
                    if (tid != iA) {
                        float4 v = own[tid];
                        v.x = fmaf(v.z, dte, v.x); v.y = fmaf(v.w, dte, v.y);
                        own[tid] = v;
                        float4 c = bb0[tid];
                        c.x = fmaf(c.z, dte, c.x); c.y = fmaf(c.w, dte, c.y);
                        bb0[tid] = c;
                        posA[tid] = make_float2(c.x, c.y);
                    }
                }
            }
            __syncthreads();                              // ---- BAR E / W2 ----
        }  // events

        // ---- step end ----
        __syncthreads();                                  // orders break-path reads vs writes
        const float dte2 = (t_e > t_c + 1e-10f) ? (t_e - t_c) : 0.0f;
        {
            float4 v = own[tid];
            v.x = fmaf(v.z, dte2, v.x); v.y = fmaf(v.w, dte2, v.y);
            own[tid] = v;
            float4 c = bb0[tid];
            c.x = fmaf(c.z, dte2, c.x); c.y = fmaf(c.w, dte2, c.y);
            bb0[tid] = c;
            posA[tid] = make_float2(c.x, c.y);
            reinterpret_cast<float4*>(g_out)[((long)(s+1)*BATCHN + bidx)*NB + tid] = v;
        }
        if (tid == 0)
            sMotion += 2.0f * sqrtf(__int_as_float(sVmax2i)) * dte2;
        __syncthreads();
    }
}

extern "C" void kernel_launch(void* const* d_in, const int* in_sizes, int n_in,
                              void* d_out, int out_size) {
    (void)in_sizes; (void)n_in; (void)out_size;
    hybrid_rollout<<<BATCHN, NTH>>>(
        (const float*)d_in[0], (const float*)d_in[1],
        (const float*)d_in[2], (const float*)d_in[3],
        (const float*)d_in[4], (const float*)d_in[5],
        (const float*)d_in[6], (const float*)d_in[7],
        (float*)d_out);
}

// round 9
// speedup vs baseline: 1.2351x; 1.2351x over previous
#include <cuda_runtime.h>
#include <cuda_bf16.h>
#include <math.h>

#define NB 256
#define BATCHN 128
#define NSTEPS 100
#define MAXEV 5
#define HID 64
#define NTH 512
#define NWARP (NTH/32)
#define SEGCAP 385
#define MARGIN 1.0f

#define BAR_SYNC(id,cnt)   asm volatile("bar.sync %0, %1;"   :: "r"(id), "r"(cnt) : "memory")

__device__ __forceinline__ float silu_f(float x) {
    return x / (1.0f + expf(-x));
}

__global__ __launch_bounds__(NTH, 1)
void hybrid_rollout(const float* __restrict__ g_state,
                    const float* __restrict__ g_radii,
                    const float* __restrict__ g_W1,
                    const float* __restrict__ g_b1,
                    const float* __restrict__ g_W2,
                    const float* __restrict__ g_b2,
                    const float* __restrict__ g_W3,
                    const float* __restrict__ g_b3,
                    float* __restrict__ g_out)
{
    __shared__ float4 own[NB];                 // this block's batch element
    __shared__ float4 bb0[NB];                 // private copy of batch element 0
    __shared__ float2 posA[NB];                // position mirror of bb0 (broad phase)
    __shared__ float4 w2q[16*HID];             // w2q[k4*HID+o] = W2[o][4k4..4k4+3]
    __shared__ float w1s[2*HID];
    __shared__ float b1s[HID], b2s[HID], w3s[HID];
    __shared__ float4 h1q[2*16];               // layer-1 activations as float4
    __shared__ float h2buf[2*HID];
    __shared__ unsigned long long redB[NWARP], redW[NWARP];
    __shared__ float vmaxW[NWARP];
    __shared__ int nCandW[NWARP];
    __shared__ int candList[NWARP*SEGCAP];     // per-warp segments, packed (lo<<8)|hi
    __shared__ int sVmax2i;                    // float bits of max speed^2 over bb0
    __shared__ float sMotion;
    __shared__ int sOverflow;
    __shared__ float sb3, srr;

    const int tid  = threadIdx.x;
    const int bidx = blockIdx.x;
    const int i0   = tid & (NB-1);
    const int half = tid >> 8;
    const int lane = tid & 31;
    const int warp = tid >> 5;

    // ---- setup ----
    if (tid < NB) {
        float4 v = reinterpret_cast<const float4*>(g_state)[bidx*NB + tid];
        own[tid] = v;
        float4 c = reinterpret_cast<const float4*>(g_state)[tid];
        bb0[tid] = c;
        posA[tid] = make_float2(c.x, c.y);
        reinterpret_cast<float4*>(g_out)[bidx*NB + tid] = v;
    }
    for (int q = tid; q < 16*HID; q += NTH) {
        int o = q & 63, k4 = q >> 6;
        const float* src = g_W2 + o*HID + k4*4;
        w2q[q] = make_float4(src[0], src[1], src[2], src[3]);
    }
    if (tid < 2*HID) w1s[tid] = g_W1[tid];
    if (tid < HID) { b1s[tid] = g_b1[tid]; b2s[tid] = g_b2[tid]; w3s[tid] = g_W3[tid]; }
    if (tid == 0) {
        sb3 = g_b3[0]; srr = g_radii[0];
        sMotion = 1e30f; sVmax2i = 0; sOverflow = 0;
    }
    __syncthreads();

    const float rr    = srr;
    const float two_r = rr + rr;
    const float cut   = two_r + 0.051f;        // exact narrow cutoff (gap>0.05 -> done)
    const float c2    = cut * cut;
    const float cute  = cut + MARGIN;          // broad-phase cutoff
    const float c2e   = cute * cute;
    const float b3v   = sb3;

    for (int s = 0; s < NSTEPS; ++s) {
        const float t_s = (float)s * 0.05f;
        const float t_e = t_s + 0.05f;
        float t_c = t_s;

        for (int ev = 0; ev < MAXEV; ++ev) {
            // ================= P0: detection =================
            const bool rebuild = (sOverflow != 0) || (sMotion >= MARGIN);
            const float4 me = bb0[i0];
            unsigned long long bk = ~0ull, wk = ~0ull;

            if (rebuild) {
                // warp-max of speed^2 (no atomics)
                float m = me.z*me.z + me.w*me.w;
                #pragma unroll
                for (int off = 16; off > 0; off >>= 1)
                    m = fmaxf(m, __shfl_down_sync(0xFFFFFFFFu, m, off));
                if (lane == 0) vmaxW[warp] = m;

                int cnt = 0;
                const int segBase = warp * SEGCAP;
                for (int d = 1 + half; d <= 128; d += 2) {
                    if (d == 128 && i0 >= 128) break;      // warp-uniform
                    int j = (i0 + d) & (NB-1);
                    float2 pj = posA[j];
                    float dx = pj.x - me.x, dy = pj.y - me.y;
                    float d2 = dx*dx + dy*dy;
                    bool push = (d2 <= c2e);
                    unsigned msk = __ballot_sync(0xFFFFFFFFu, push);
                    if (push) {
                        int lo = (i0 < j) ? i0 : j;
                        int hi = (i0 < j) ? j : i0;
                        int slot = cnt + __popc(msk & ((1u << lane) - 1u));
                        if (slot < SEGCAP) candList[segBase + slot] = (lo << 8) | hi;
                        float4 oj = bb0[j];
                        float dvx = oj.z - me.z, dvy = oj.w - me.w;
                        if (dvx*dx + dvy*dy < 0.0f && d2 <= c2) {
                            unsigned long long key =
                                ((unsigned long long)__float_as_uint(d2) << 32) |
                                (unsigned)((lo << 8) | hi);
                            if (key < bk) bk = key;
                        }
                    }
                    cnt += __popc(msk);
                }
                if (lane == 0) nCandW[warp] = cnt;
            } else {
                const int seg  = tid & (NWARP-1);
                const int e0   = tid >> 4;                 // 0..31
                int n = nCandW[seg]; if (n > SEGCAP) n = SEGCAP;
                const int base = seg * SEGCAP;
                for (int e = e0; e < n; e += 32) {
                    int p = candList[base + e];
                    int lo = p >> 8, hi = p & 255;
                    float4 si = bb0[lo], sj = bb0[hi];
                    float dx = sj.x - si.x, dy = sj.y - si.y;
                    float d2 = dx*dx + dy*dy;
                    float dvx = sj.z - si.z, dvy = sj.w - si.w;
                    if (dvx*dx + dvy*dy < 0.0f && d2 <= c2) {
                        unsigned long long key =
                            ((unsigned long long)__float_as_uint(d2) << 32) | (unsigned)p;
                        if (key < bk) bk = key;
                    }
                }
            }

            // wall candidates
            if (half == 0) {
                float gs[4]; bool vs[4];
                gs[0] = me.x - rr;          vs[0] = me.z < 0.0f;
                gs[1] = 10.0f - me.x - rr;  vs[1] = me.z > 0.0f;
                gs[2] = me.y - rr;          vs[2] = me.w < 0.0f;
                gs[3] = 10.0f - me.y - rr;  vs[3] = me.w > 0.0f;
                #pragma unroll
                for (int w = 0; w < 4; ++w) {
                    if (vs[w]) {
                        unsigned u = __float_as_uint(gs[w]);
                        u = (u & 0x80000000u) ? ~u : (u | 0x80000000u);
                        unsigned long long key = ((unsigned long long)u << 32) | (unsigned)(i0*4 + w);
                        if (key < wk) wk = key;
                    }
                }
            }

            // warp tree -> lane0 STS -> BAR -> redundant 16-way butterfly fold
            #pragma unroll
            for (int off = 16; off > 0; off >>= 1) {
                unsigned long long ob = __shfl_down_sync(0xFFFFFFFFu, bk, off);
                unsigned long long ow = __shfl_down_sync(0xFFFFFFFFu, wk, off);
                if (ob < bk) bk = ob;
                if (ow < wk) wk = ow;
            }
            if (lane == 0) { redB[warp] = bk; redW[warp] = wk; }
            __syncthreads();                              // ---- BAR A ----

            if (rebuild && tid == NTH-1) {
                float vm = vmaxW[0];
                #pragma unroll
                for (int w = 1; w < NWARP; ++w) vm = fmaxf(vm, vmaxW[w]);
                sVmax2i = __float_as_int(vm);
                int ov = 0;
                #pragma unroll
                for (int w = 0; w < NWARP; ++w) ov |= (nCandW[w] > SEGCAP);
                if (ov) sOverflow = 1;
                sMotion = 0.0f;
            }

            bk = redB[lane & (NWARP-1)];
            wk = redW[lane & (NWARP-1)];
            #pragma unroll
            for (int off = 8; off > 0; off >>= 1) {
                unsigned long long ob = __shfl_xor_sync(0xFFFFFFFFu, bk, off);
                unsigned long long ow = __shfl_xor_sync(0xFFFFFFFFu, wk, off);
                if (ob < bk) bk = ob;
                if (ow < wk) wk = ow;
            }

            float gapB = 1e30f, gapW = 1e30f;
            if (bk != ~0ull) gapB = sqrtf(__uint_as_float((unsigned)(bk >> 32))) - two_r;
            if (wk != ~0ull) {
                unsigned u = (unsigned)(wk >> 32);
                u = (u & 0x80000000u) ? (u ^ 0x80000000u) : ~u;
                gapW = __uint_as_float(u);
            }
            const bool  is_ball = (gapB <= gapW);
            const float gap     = is_ball ? gapB : gapW;
            if (gap > 0.05f) break;                        // no_event -> done

            // redundant decode + flags on ALL threads
            int iA, iB = 0, wsel = 0;
            float app;
            if (is_ball) {
                iA = (int)(((unsigned)bk >> 8) & 255u);
                iB = (int)((unsigned)bk & 255u);
                float4 pi = bb0[iA], pj = bb0[iB];
                float nx = pj.x - pi.x, ny = pj.y - pi.y;
                float L = sqrtf(nx*nx + ny*ny);
                app = -(((pj.z - pi.z)*nx)/L + ((pj.w - pi.w)*ny)/L);
            } else {
                iA = (int)((unsigned)wk >> 2);
                wsel = (int)((unsigned)wk & 3u);
                float4 pi = bb0[iA];
                app = fabsf(fmaxf(pi.z, pi.w));
            }
            const float t_ev  = t_c + gap / fmaxf(app, 1e-6f);
            const bool case_a = (gap <= 0.0f);
            const bool case_b = (!case_a) && (app > 1e-6f) && (t_ev < t_e);
            if (!case_a && !case_b) break;                 // done
            const float dte = case_b ? ((t_ev > t_c + 1e-10f) ? (t_ev - t_c) : 0.0f) : 0.0f;
            if (case_b) t_c = t_ev;

            if (is_ball) {
                // warps 0-3: MLP (named bars among themselves);
                // warps 4-11: integrate everything except iA,iB;
                // warp 15 thread 511: sMotion;
                // single full barrier at the end (BAR E).
                if (tid < 2*HID) {
                    int sel = tid >> 6, o = tid & (HID-1);
                    const float4* S = sel ? bb0 : own;
                    float4 si = S[iA], sj = S[iB];
                    float six = fmaf(si.z, dte, si.x), siy = fmaf(si.w, dte, si.y);
                    float sjx = fmaf(sj.z, dte, sj.x), sjy = fmaf(sj.w, dte, sj.y);
                    float dx = sjx - six, dy = sjy - siy;
                    float dist = fmaxf(sqrtf(dx*dx + dy*dy), 1e-8f);
                    float nx = dx / dist, ny = dy / dist;
                    float ap = (sj.z - si.z)*nx + (sj.w - si.w)*ny;
                    float pre = dist*w1s[2*o] + ap*w1s[2*o+1] + b1s[o];
                    reinterpret_cast<float*>(h1q)[sel*HID + o] = silu_f(pre);
                    BAR_SYNC(3, 128);                     // ---- h1 ready (warps 0-3) ----
                    const float4* H = &h1q[sel*16];
                    float a0 = 0.f, a1 = 0.f;
                    #pragma unroll 4
                    for (int k4 = 0; k4 < 16; k4 += 2) {
                        float4 w0 = w2q[(k4+0)*HID + o], hh0 = H[k4+0];
                        a0 = fmaf(w0.x,hh0.x,a0); a0 = fmaf(w0.y,hh0.y,a0);
                        a0 = fmaf(w0.z,hh0.z,a0); a0 = fmaf(w0.w,hh0.w,a0);
                        float4 w1v = w2q[(k4+1)*HID + o], hh1 = H[k4+1];
                        a1 = fmaf(w1v.x,hh1.x,a1); a1 = fmaf(w1v.y,hh1.y,a1);
                        a1 = fmaf(w1v.z,hh1.z,a1); a1 = fmaf(w1v.w,hh1.w,a1);
                    }
                    float acc = (b2s[o] + a0) + a1;
                    h2buf[sel*HID + o] = w3s[o] * silu_f(acc);
                    BAR_SYNC(3, 128);                     // ---- h2 ready (warps 0-3) ----
                    if (warp == 0 || warp == 2) {
                        int sl = warp >> 1;
                        float v = h2buf[sl*HID + lane] + h2buf[sl*HID + 32 + lane];
                        #pragma unroll
                        for (int off = 16; off > 0; off >>= 1)
                            v += __shfl_down_sync(0xFFFFFFFFu, v, off);
                        if (lane == 0) {
                            float impv = v + b3v;
                            float4* S2 = sl ? bb0 : own;
                            float4 ti = S2[iA], tj = S2[iB];   // still pre-event values
                            float tix = fmaf(ti.z, dte, ti.x), tiy = fmaf(ti.w, dte, ti.y);
                            float tjx = fmaf(tj.z, dte, tj.x), tjy = fmaf(tj.w, dte, tj.y);
                            float ddx = tjx - tix, ddy = tjy - tiy;
                            float dst = fmaxf(sqrtf(ddx*ddx + ddy*ddy), 1e-8f);
                            float nnx = ddx/dst, nny = ddy/dst;
                            float niz = ti.z + impv*nnx, niw = ti.w + impv*nny;
                            float njz = tj.z - impv*nnx, njw = tj.w - impv*nny;
                            S2[iA] = make_float4(tix, tiy, niz, niw);
                            S2[iB] = make_float4(tjx, tjy, njz, njw);
                            if (sl == 1) {
                                posA[iA] = make_float2(tix, tiy);
                                posA[iB] = make_float2(tjx, tjy);
                                float sp = fmaxf(niz*niz + niw*niw, njz*njz + njw*njw);
                                atomicMax(&sVmax2i, __float_as_int(sp));
                            }
                        }
                    }
                } else if (tid < 384) {
                    int b = tid - 128;
                    if (b != iA && b != iB) {
                        float4 v = own[b];
                        v.x = fmaf(v.z, dte, v.x); v.y = fmaf(v.w, dte, v.y);
                        own[b] = v;
                        float4 c = bb0[b];
                        c.x = fmaf(c.z, dte, c.x); c.y = fmaf(c.w, dte, c.y);
                        bb0[b] = c;
                        posA[b] = make_float2(c.x, c.y);
                    }
                } else if (tid == NTH-1) {
                    sMotion += 2.0f * sqrtf(__int_as_float(sVmax2i)) * dte;
                }
                __syncthreads();                          // ---- BAR E ----
            } else {
                // wall: compute results + integrate (b != iA) pre-barrier; write iA post-barrier
                float4 res; float pen = 0.0f;
                if (tid < 2) {
                    const float4 si = tid ? bb0[iA] : own[iA];
                    float six = fmaf(si.z, dte, si.x), siy = fmaf(si.w, dte, si.y);
                    float wnx = 0.0f, wny = 0.0f, wp = 0.0f;
                    if      (wsel == 0) { wnx =  1.0f; }
                    else if (wsel == 1) { wnx = -1.0f; wp = -10.0f; }
                    else if (wsel == 2) { wny =  1.0f; }
                    else                { wny = -1.0f; wp = -10.0f; }
                    float vn  = si.z*wnx + si.w*wny;
                    float nvx = si.z - 2.0f*vn*wnx;
                    float nvy = si.w - 2.0f*vn*wny;
                    float pn  = six*wnx + siy*wny;
                    pen = fmaxf(wp + rr - pn, 0.0f);
                    res = make_float4(six + pen*wnx, siy + pen*wny, nvx, nvy);
                } else if (tid >= 128 && tid < 384) {
                    int b = tid - 128;
                    if (b != iA) {
                        float4 v = own[b];
                        v.x = fmaf(v.z, dte, v.x); v.y = fmaf(v.w, dte, v.y);
                        own[b] = v;
                        float4 c = bb0[b];
                        c.x = fmaf(c.z, dte, c.x); c.y = fmaf(c.w, dte, c.y);
                        bb0[b] = c;
                        posA[b] = make_float2(c.x, c.y);
                    }
                }
                __syncthreads();                          // ---- BAR W1 (decode reads done)
                if (tid < 2) {
                    float4* S = tid ? bb0 : own;
                    S[iA] = res;
                    if (tid == 1) {
                        posA[iA] = make_float2(res.x, res.y);
                        sMotion += 2.0f * sqrtf(__int_as_float(sVmax2i)) * dte + pen;
                    }
                }
                __syncthreads();                          // ---- BAR W2 ----
            }
        }  // events

        // ---- step end ----
        __syncthreads();                                  // orders break-path reads vs writes
        const float dte2 = (t_e > t_c + 1e-10f) ? (t_e - t_c) : 0.0f;
        if (tid < NB) {
            float4 v = own[tid];
            v.x = fmaf(v.z, dte2, v.x); v.y = fmaf(v.w, dte2, v.y);
            own[tid] = v;
            float4 c = bb0[tid];
            c.x = fmaf(c.z, dte2, c.x); c.y = fmaf(c.w, dte2, c.y);
            bb0[tid] = c;
            posA[tid] = make_float2(c.x, c.y);
            reinterpret_cast<float4*>(g_out)[((long)(s+1)*BATCHN + bidx)*NB + tid] = v;
        }
        if (tid == 0)
            sMotion += 2.0f * sqrtf(__int_as_float(sVmax2i)) * dte2;
        __syncthreads();
    }
}

extern "C" void kernel_launch(void* const* d_in, const int* in_sizes, int n_in,
                              void* d_out, int out_size) {
    (void)in_sizes; (void)n_in; (void)out_size;
    hybrid_rollout<<<BATCHN, NTH>>>(
        (const float*)d_in[0], (const float*)d_in[1],
        (const float*)d_in[2], (const float*)d_in[3],
        (const float*)d_in[4], (const float*)d_in[5],
        (const float*)d_in[6], (const float*)d_in[7],
        (float*)d_out);
}